// round 1
// baseline (speedup 1.0000x reference)
#include <cuda_runtime.h>
#include <cuda_bf16.h>
#include <math.h>

// Problem constants
constexpr int Dm = 1024;   // dim == seq len L
constexpr int Ns = 16;     // SSM state size

// ---------------- scratch (static device globals: allocation-free) ----------
__device__ float g_p[2 * Dm * Dm];    // [0]=xm, [1]=xg(silu'd)
__device__ float g_xc[Dm * Dm];       // conv output (silu'd)
__device__ float g_delta[Dm * Dm];    // softplus(xc @ W_delta)
__device__ float g_Bm[Dm * Ns];
__device__ float g_Cm[Dm * Ns];
__device__ float g_y[Dm * Dm];        // ssm output
__device__ float g_t[Dm * Dm];        // y @ xg^T
__device__ float g_WdT[Dm * Dm];      // W_delta transposed

__device__ __forceinline__ float sigmoidf_(float x) {
    return 1.0f / (1.0f + expf(-x));
}

// ---------------- transpose (for W_delta) -----------------------------------
__global__ void __launch_bounds__(256) transpose_k(const float* __restrict__ In,
                                                   float* __restrict__ Out) {
    __shared__ float t[32][33];
    int x0 = blockIdx.x * 32, y0 = blockIdx.y * 32;
    int tx = threadIdx.x;
    for (int j = threadIdx.y; j < 32; j += 8)
        t[j][tx] = In[(y0 + j) * Dm + x0 + tx];
    __syncthreads();
    for (int j = threadIdx.y; j < 32; j += 8)
        Out[(x0 + j) * Dm + y0 + tx] = t[tx][j];
}

// ---------------- generic tiled NT GEMM: C[m,n] = sum_k A[m,k]*B[n,k] --------
// EPI: 0 = none, 1 = +bias, 2 = +bias then silu, 3 = softplus
template <int EPI>
__global__ void __launch_bounds__(256) gemm_nt(const float* __restrict__ A,
                                               const float* __restrict__ B,
                                               const float* __restrict__ bias,
                                               float* __restrict__ C,
                                               int M, int Nn, int K) {
    __shared__ float As[16][65];
    __shared__ float Bs[16][65];
    const int tid = threadIdx.x;
    const int m0 = blockIdx.y * 64, n0 = blockIdx.x * 64;
    const int lr = tid >> 2;           // 0..63
    const int lc = (tid & 3) << 2;     // 0,4,8,12
    const int ty = tid >> 4, tx = tid & 15;
    float acc[4][4] = {};
    const float* Ap = A + (size_t)(m0 + lr) * K + lc;
    const float* Bp = B + (size_t)(n0 + lr) * K + lc;

    for (int k0 = 0; k0 < K; k0 += 16) {
        float4 av = *(const float4*)(Ap + k0);
        float4 bv = *(const float4*)(Bp + k0);
        As[lc + 0][lr] = av.x; As[lc + 1][lr] = av.y;
        As[lc + 2][lr] = av.z; As[lc + 3][lr] = av.w;
        Bs[lc + 0][lr] = bv.x; Bs[lc + 1][lr] = bv.y;
        Bs[lc + 2][lr] = bv.z; Bs[lc + 3][lr] = bv.w;
        __syncthreads();
#pragma unroll
        for (int k = 0; k < 16; k++) {
            float a[4], b[4];
#pragma unroll
            for (int i = 0; i < 4; i++) a[i] = As[k][ty * 4 + i];
#pragma unroll
            for (int j = 0; j < 4; j++) b[j] = Bs[k][tx * 4 + j];
#pragma unroll
            for (int i = 0; i < 4; i++)
#pragma unroll
                for (int j = 0; j < 4; j++)
                    acc[i][j] = fmaf(a[i], b[j], acc[i][j]);
        }
        __syncthreads();
    }

#pragma unroll
    for (int i = 0; i < 4; i++) {
        int m = m0 + ty * 4 + i;
#pragma unroll
        for (int j = 0; j < 4; j++) {
            int n = n0 + tx * 4 + j;
            float c = acc[i][j];
            if (EPI == 1 || EPI == 2) c += bias[n];
            if (EPI == 2) c = c * sigmoidf_(c);
            if (EPI == 3) c = fmaxf(c, 0.0f) + log1pf(expf(-fabsf(c)));
            C[(size_t)m * Nn + n] = c;
        }
    }
}

// ---------------- conv1d (channels=L, length=D, K=3, pad=1) + bias + silu ----
// out[o,d] = silu( sum_i sum_kk W[o,i,kk] * X[i, d+kk-1] + bias[o] )
__global__ void __launch_bounds__(256) conv_silu(const float* __restrict__ W,   // [D][D][3]
                                                 const float* __restrict__ X,   // [D][D]
                                                 const float* __restrict__ bias,
                                                 float* __restrict__ C) {
    __shared__ float Ws[3][16][65];
    __shared__ float Xs[16][68];
    const int tid = threadIdx.x;
    const int o0 = blockIdx.y * 64, d0 = blockIdx.x * 64;
    const int ty = tid >> 4, tx = tid & 15;
    float acc[4][4] = {};

    for (int i0 = 0; i0 < Dm; i0 += 16) {
        // load weights: Ws[kk][i][o]
        {
            int i = tid >> 4;              // 0..15
            int obase = (tid & 15) * 4;    // 0..60
#pragma unroll
            for (int kk = 0; kk < 3; kk++)
#pragma unroll
                for (int j = 0; j < 4; j++)
                    Ws[kk][i][obase + j] =
                        W[(size_t)(o0 + obase + j) * (Dm * 3) + (i0 + i) * 3 + kk];
        }
        // load X tile rows i0..i0+15, cols d0-1..d0+64 (66 cols, zero-padded)
        for (int idx = tid; idx < 16 * 66; idx += 256) {
            int i = idx / 66, c = idx % 66;
            int gd = d0 - 1 + c;
            Xs[i][c] = (gd >= 0 && gd < Dm) ? X[(size_t)(i0 + i) * Dm + gd] : 0.0f;
        }
        __syncthreads();
#pragma unroll
        for (int k = 0; k < 16; k++) {
            float a0[4], a1[4], a2[4], b[6];
#pragma unroll
            for (int i = 0; i < 4; i++) {
                a0[i] = Ws[0][k][ty * 4 + i];
                a1[i] = Ws[1][k][ty * 4 + i];
                a2[i] = Ws[2][k][ty * 4 + i];
            }
#pragma unroll
            for (int j = 0; j < 6; j++) b[j] = Xs[k][tx * 4 + j];
#pragma unroll
            for (int i = 0; i < 4; i++)
#pragma unroll
                for (int j = 0; j < 4; j++) {
                    acc[i][j] = fmaf(a0[i], b[j], acc[i][j]);
                    acc[i][j] = fmaf(a1[i], b[j + 1], acc[i][j]);
                    acc[i][j] = fmaf(a2[i], b[j + 2], acc[i][j]);
                }
        }
        __syncthreads();
    }

#pragma unroll
    for (int i = 0; i < 4; i++) {
        int o = o0 + ty * 4 + i;
        float bb = bias[o];
#pragma unroll
        for (int j = 0; j < 4; j++) {
            int d = d0 + tx * 4 + j;
            float c = acc[i][j] + bb;
            c = c * sigmoidf_(c);
            C[(size_t)o * Dm + d] = c;
        }
    }
}

// ---------------- B/C projections: [L,D] @ [D,16] ---------------------------
__global__ void __launch_bounds__(256) bc_kernel(const float* __restrict__ Xc,
                                                 const float* __restrict__ WB,
                                                 const float* __restrict__ WC,
                                                 float* __restrict__ Bo,
                                                 float* __restrict__ Co) {
    __shared__ float row[Dm];
    const int l = blockIdx.x;
    for (int k = threadIdx.x; k < Dm; k += 256) row[k] = Xc[(size_t)l * Dm + k];
    __syncthreads();
    const int part = threadIdx.x & 7;     // 8 partials per output
    const int out = threadIdx.x >> 3;     // 0..31 (16 B + 16 C)
    const int n = out & 15;
    const float* W = (out < 16) ? WB : WC;
    float s = 0.0f;
    for (int k = part; k < Dm; k += 8) s = fmaf(row[k], W[k * Ns + n], s);
#pragma unroll
    for (int off = 4; off; off >>= 1) s += __shfl_down_sync(0xffffffffu, s, off, 8);
    if (part == 0) {
        if (out < 16) Bo[l * Ns + n] = s;
        else          Co[l * Ns + n] = s;
    }
}

// ---------------- selective scan ---------------------------------------------
// One thread per (d,n). h[l] = exp(delta[l,d]*A[d,n])*h[l-1] + delta[l,d]*xc[l,d]*B[l,n]
// y[l,d] = sum_n h[l,d,n] * C[l,n]
__global__ void __launch_bounds__(128) scan_kernel(const float* __restrict__ delta,
                                                   const float* __restrict__ Xc,
                                                   const float* __restrict__ Bm,
                                                   const float* __restrict__ Cm,
                                                   const float* __restrict__ Alog,
                                                   float* __restrict__ Y) {
    const int n = threadIdx.x & 15;
    const int d = blockIdx.x * 8 + (threadIdx.x >> 4);
    const float a = -expf(Alog[d * Ns + n]);
    float h = 0.0f;
    for (int l = 0; l < Dm; l++) {
        float de = delta[(size_t)l * Dm + d];
        float xv = Xc[(size_t)l * Dm + d];
        float bv = Bm[l * Ns + n];
        float cv = Cm[l * Ns + n];
        float e = __expf(de * a);          // off the h critical chain
        h = fmaf(e, h, de * xv * bv);
        float p = h * cv;
#pragma unroll
        for (int off = 8; off; off >>= 1) p += __shfl_down_sync(0xffffffffu, p, off, 16);
        if (n == 0) Y[(size_t)l * Dm + d] = p;
    }
}

// ---------------- launch ------------------------------------------------------
extern "C" void kernel_launch(void* const* d_in, const int* in_sizes, int n_in,
                              void* d_out, int out_size) {
    const float* x    = (const float*)d_in[0];  // [2,1024,1024]
    const float* Wp   = (const float*)d_in[1];  // [1024,1024]
    const float* bp   = (const float*)d_in[2];  // [1024]
    const float* cw   = (const float*)d_in[3];  // [1024,1024,3]
    const float* cb   = (const float*)d_in[4];  // [1024]
    const float* Alog = (const float*)d_in[5];  // [1024,16]
    const float* Wd   = (const float*)d_in[6];  // [1024,1024]
    const float* WB   = (const float*)d_in[7];  // [1024,16]
    const float* WC   = (const float*)d_in[8];  // [1024,16]
    float* out = (float*)d_out;

    float *p, *xc, *del, *Bm, *Cm, *y, *t, *wdt;
    cudaGetSymbolAddress((void**)&p,   g_p);
    cudaGetSymbolAddress((void**)&xc,  g_xc);
    cudaGetSymbolAddress((void**)&del, g_delta);
    cudaGetSymbolAddress((void**)&Bm,  g_Bm);
    cudaGetSymbolAddress((void**)&Cm,  g_Cm);
    cudaGetSymbolAddress((void**)&y,   g_y);
    cudaGetSymbolAddress((void**)&t,   g_t);
    cudaGetSymbolAddress((void**)&wdt, g_WdT);

    dim3 g16(16, 16);

    // W_delta^T so the delta GEMM is NT like everything else
    transpose_k<<<dim3(32, 32), dim3(32, 8)>>>(Wd, wdt);

    // shared input projection: xm = x0@Wp^T+b ; xg = silu(x1@Wp^T+b)
    gemm_nt<1><<<g16, 256>>>(x,            Wp, bp, p,            Dm, Dm, Dm);
    gemm_nt<2><<<g16, 256>>>(x + Dm * Dm,  Wp, bp, p + Dm * Dm,  Dm, Dm, Dm);

    // conv1d + bias + silu
    conv_silu<<<g16, 256>>>(cw, p, cb, xc);

    // delta = softplus(xc @ W_delta)
    gemm_nt<3><<<g16, 256>>>(xc, wdt, nullptr, del, Dm, Dm, Dm);

    // B, C projections
    bc_kernel<<<Dm, 256>>>(xc, WB, WC, Bm, Cm);

    // selective scan -> y
    scan_kernel<<<Dm / 8, 128>>>(del, xc, Bm, Cm, Alog, y);

    // y @ xg^T
    gemm_nt<0><<<g16, 256>>>(y, p + Dm * Dm, nullptr, t, Dm, Dm, Dm);

    // final shared proj
    gemm_nt<1><<<g16, 256>>>(t, Wp, bp, out, Dm, Dm, Dm);
}

// round 2
// speedup vs baseline: 1.8877x; 1.8877x over previous
#include <cuda_runtime.h>
#include <cuda_bf16.h>
#include <math.h>
#include <stdint.h>

constexpr int Dm = 1024;   // dim == seq len L
constexpr int Ns = 16;     // SSM state size
constexpr int KC = 3 * Dm; // conv GEMM K = 3072

typedef __nv_bfloat16 bf16;

// ---------------- scratch (static device globals: allocation-free) ----------
__device__ bf16 g_xhi[2 * Dm * Dm], g_xlo[2 * Dm * Dm];
__device__ bf16 g_Wphi[Dm * Dm],   g_Wplo[Dm * Dm];
__device__ bf16 g_cwhi[Dm * KC],   g_cwlo[Dm * KC];
__device__ bf16 g_WdThi[Dm * Dm],  g_WdTlo[Dm * Dm];
__device__ float g_p0[Dm * Dm];
__device__ bf16 g_xghi[Dm * Dm],   g_xglo[Dm * Dm];
__device__ bf16 g_cBhi[Dm * KC],   g_cBlo[Dm * KC];
__device__ float g_xc[Dm * Dm];
__device__ bf16 g_xchi[Dm * Dm],   g_xclo[Dm * Dm];
__device__ float g_delta[Dm * Dm];
__device__ float g_Bm[Dm * Ns], g_Cm[Dm * Ns];
__device__ bf16 g_yhi[Dm * Dm],    g_ylo[Dm * Dm];
__device__ bf16 g_thi[Dm * Dm],    g_tlo[Dm * Dm];

__device__ __forceinline__ float sigmoidf_(float x) {
    return 1.0f / (1.0f + expf(-x));
}

// ---------------- fp32 -> (hi,lo) bf16 split --------------------------------
__global__ void __launch_bounds__(256) split_k(const float* __restrict__ in,
                                               bf16* __restrict__ hi,
                                               bf16* __restrict__ lo, int n) {
    int i = (blockIdx.x * 256 + threadIdx.x) * 4;
    if (i >= n) return;
    float4 v = *(const float4*)(in + i);
    float vv[4] = {v.x, v.y, v.z, v.w};
#pragma unroll
    for (int j = 0; j < 4; j++) {
        bf16 h = __float2bfloat16(vv[j]);
        hi[i + j] = h;
        lo[i + j] = __float2bfloat16(vv[j] - __bfloat162float(h));
    }
}

// ---------------- transpose + split (for W_delta) ---------------------------
__global__ void __launch_bounds__(256) transpose_split_k(const float* __restrict__ In,
                                                         bf16* __restrict__ hi,
                                                         bf16* __restrict__ lo) {
    __shared__ float t[32][33];
    int x0 = blockIdx.x * 32, y0 = blockIdx.y * 32;
    int tx = threadIdx.x;
    for (int j = threadIdx.y; j < 32; j += 8)
        t[j][tx] = In[(y0 + j) * Dm + x0 + tx];
    __syncthreads();
    for (int j = threadIdx.y; j < 32; j += 8) {
        float v = t[tx][j];
        bf16 h = __float2bfloat16(v);
        size_t idx = (size_t)(x0 + j) * Dm + y0 + tx;
        hi[idx] = h;
        lo[idx] = __float2bfloat16(v - __bfloat162float(h));
    }
}

// ---------------- build conv B matrix: B[d, i*3+kk] = p0[i, d-1+kk] ----------
__global__ void __launch_bounds__(256) conv_b_build(const float* __restrict__ P0,
                                                    bf16* __restrict__ hi,
                                                    bf16* __restrict__ lo) {
    __shared__ float Xs[32][35];
    int d0 = blockIdx.x * 32, i0 = blockIdx.y * 32;
    int tid = threadIdx.x;
    for (int idx = tid; idx < 32 * 34; idx += 256) {
        int r = idx / 34, c = idx % 34;
        int gd = d0 - 1 + c;
        Xs[r][c] = (gd >= 0 && gd < Dm) ? P0[(size_t)(i0 + r) * Dm + gd] : 0.0f;
    }
    __syncthreads();
    int i = tid & 31;
    for (int dl = tid >> 5; dl < 32; dl += 8) {
        size_t base = (size_t)(d0 + dl) * KC + (size_t)(i0 + i) * 3;
#pragma unroll
        for (int kk = 0; kk < 3; kk++) {
            float x = Xs[i][dl + kk];
            bf16 h = __float2bfloat16(x);
            hi[base + kk] = h;
            lo[base + kk] = __float2bfloat16(x - __bfloat162float(h));
        }
    }
}

// ---------------- bf16-split tensor-core NT GEMM -----------------------------
// C[m,n] = sum_k A[m,k] * B[n,k], with A = Ah + Al, B = Bh + Bl (bf16).
// C ~= Ah*Bh + Ah*Bl + Al*Bh  (3 mma accumulations, fp32 accumulator)
// EPI: 0 none, 1 +bias, 2 +bias then silu, 3 softplus. BIASROW: bias[m] vs bias[n].
#define MMA_BF16(c, a, b)                                                        \
    asm volatile(                                                                \
        "mma.sync.aligned.m16n8k16.row.col.f32.bf16.bf16.f32 "                   \
        "{%0,%1,%2,%3},{%4,%5,%6,%7},{%8,%9},{%0,%1,%2,%3};"                     \
        : "+f"(c[0]), "+f"(c[1]), "+f"(c[2]), "+f"(c[3])                         \
        : "r"(a[0]), "r"(a[1]), "r"(a[2]), "r"(a[3]), "r"(b[0]), "r"(b[1]))

template <int EPI, bool BIASROW, bool WF32, bool WSPLIT>
__global__ void __launch_bounds__(256) gemm_bf3(
    const bf16* __restrict__ Ah, const bf16* __restrict__ Al,
    const bf16* __restrict__ Bh, const bf16* __restrict__ Bl,
    const float* __restrict__ bias,
    float* __restrict__ Cf, bf16* __restrict__ Chi, bf16* __restrict__ Clo,
    int M, int N, int K)
{
    __shared__ __align__(16) bf16 As[2][128][40];
    __shared__ __align__(16) bf16 Bs[2][64][40];
    const int tid = threadIdx.x;
    const int m0 = blockIdx.y * 128, n0 = blockIdx.x * 64;
    const int lane = tid & 31, warp = tid >> 5;
    const int wm = (warp >> 1) * 32, wn = (warp & 1) * 32;
    const int fr = lane >> 2, fc = (lane & 3) * 2;

    float acc[2][4][4];
#pragma unroll
    for (int a = 0; a < 2; a++)
#pragma unroll
        for (int b = 0; b < 4; b++)
#pragma unroll
            for (int c = 0; c < 4; c++) acc[a][b][c] = 0.0f;

    // global load coordinates (int4 = 8 bf16 chunks)
    const int am0 = tid >> 2,          ak0 = (tid & 3) * 8;       // A chunk 0
    const int am1 = (tid + 256) >> 2,  ak1 = ((tid + 256) & 3) * 8; // A chunk 1
    const int bn  = tid >> 2,          bk  = (tid & 3) * 8;       // B chunk

    const char* pAh0 = (const char*)(Ah + (size_t)(m0 + am0) * K + ak0);
    const char* pAh1 = (const char*)(Ah + (size_t)(m0 + am1) * K + ak1);
    const char* pAl0 = (const char*)(Al + (size_t)(m0 + am0) * K + ak0);
    const char* pAl1 = (const char*)(Al + (size_t)(m0 + am1) * K + ak1);
    const char* pBh  = (const char*)(Bh + (size_t)(n0 + bn) * K + bk);
    const char* pBl  = (const char*)(Bl + (size_t)(n0 + bn) * K + bk);

    int4 rAh0 = *(const int4*)pAh0;
    int4 rAh1 = *(const int4*)pAh1;
    int4 rAl0 = *(const int4*)pAl0;
    int4 rAl1 = *(const int4*)pAl1;
    int4 rBh  = *(const int4*)pBh;
    int4 rBl  = *(const int4*)pBl;

    for (int k0 = 0; k0 < K; k0 += 32) {
        *(int4*)&As[0][am0][ak0] = rAh0;
        *(int4*)&As[0][am1][ak1] = rAh1;
        *(int4*)&As[1][am0][ak0] = rAl0;
        *(int4*)&As[1][am1][ak1] = rAl1;
        *(int4*)&Bs[0][bn][bk]   = rBh;
        *(int4*)&Bs[1][bn][bk]   = rBl;
        __syncthreads();

        if (k0 + 32 < K) {
            size_t off = (size_t)(k0 + 32) * sizeof(bf16);
            rAh0 = *(const int4*)(pAh0 + off);
            rAh1 = *(const int4*)(pAh1 + off);
            rAl0 = *(const int4*)(pAl0 + off);
            rAl1 = *(const int4*)(pAl1 + off);
            rBh  = *(const int4*)(pBh + off);
            rBl  = *(const int4*)(pBl + off);
        }

#pragma unroll
        for (int s = 0; s < 2; s++) {
            const int ks = s * 16;
            uint32_t ah[2][4], al[2][4], bh[4][2], bl[4][2];
#pragma unroll
            for (int mi = 0; mi < 2; mi++) {
                int mb = wm + mi * 16;
                ah[mi][0] = *(const uint32_t*)&As[0][mb + fr][ks + fc];
                ah[mi][1] = *(const uint32_t*)&As[0][mb + 8 + fr][ks + fc];
                ah[mi][2] = *(const uint32_t*)&As[0][mb + fr][ks + fc + 8];
                ah[mi][3] = *(const uint32_t*)&As[0][mb + 8 + fr][ks + fc + 8];
                al[mi][0] = *(const uint32_t*)&As[1][mb + fr][ks + fc];
                al[mi][1] = *(const uint32_t*)&As[1][mb + 8 + fr][ks + fc];
                al[mi][2] = *(const uint32_t*)&As[1][mb + fr][ks + fc + 8];
                al[mi][3] = *(const uint32_t*)&As[1][mb + 8 + fr][ks + fc + 8];
            }
#pragma unroll
            for (int ni = 0; ni < 4; ni++) {
                int nb = wn + ni * 8 + fr;
                bh[ni][0] = *(const uint32_t*)&Bs[0][nb][ks + fc];
                bh[ni][1] = *(const uint32_t*)&Bs[0][nb][ks + fc + 8];
                bl[ni][0] = *(const uint32_t*)&Bs[1][nb][ks + fc];
                bl[ni][1] = *(const uint32_t*)&Bs[1][nb][ks + fc + 8];
            }
#pragma unroll
            for (int mi = 0; mi < 2; mi++)
#pragma unroll
                for (int ni = 0; ni < 4; ni++) {
                    MMA_BF16(acc[mi][ni], ah[mi], bh[ni]);
                    MMA_BF16(acc[mi][ni], ah[mi], bl[ni]);
                    MMA_BF16(acc[mi][ni], al[mi], bh[ni]);
                }
        }
        __syncthreads();
    }

    // epilogue
#pragma unroll
    for (int mi = 0; mi < 2; mi++) {
#pragma unroll
        for (int rg = 0; rg < 2; rg++) {
            int m = m0 + wm + mi * 16 + fr + rg * 8;
#pragma unroll
            for (int ni = 0; ni < 4; ni++) {
                int n = n0 + wn + ni * 8 + fc;
                float v0 = acc[mi][ni][rg * 2 + 0];
                float v1 = acc[mi][ni][rg * 2 + 1];
                if (EPI == 1 || EPI == 2) {
                    if (BIASROW) { float b = bias[m]; v0 += b; v1 += b; }
                    else         { v0 += bias[n]; v1 += bias[n + 1]; }
                }
                if (EPI == 2) { v0 *= sigmoidf_(v0); v1 *= sigmoidf_(v1); }
                if (EPI == 3) {
                    v0 = fmaxf(v0, 0.0f) + log1pf(expf(-fabsf(v0)));
                    v1 = fmaxf(v1, 0.0f) + log1pf(expf(-fabsf(v1)));
                }
                size_t idx = (size_t)m * N + n;
                if (WF32) *(float2*)&Cf[idx] = make_float2(v0, v1);
                if (WSPLIT) {
                    bf16 h0 = __float2bfloat16(v0);
                    bf16 h1 = __float2bfloat16(v1);
                    __nv_bfloat162 hh; hh.x = h0; hh.y = h1;
                    __nv_bfloat162 ll;
                    ll.x = __float2bfloat16(v0 - __bfloat162float(h0));
                    ll.y = __float2bfloat16(v1 - __bfloat162float(h1));
                    *(__nv_bfloat162*)&Chi[idx] = hh;
                    *(__nv_bfloat162*)&Clo[idx] = ll;
                }
            }
        }
    }
}

// ---------------- B/C projections: [L,D] @ [D,16] ---------------------------
__global__ void __launch_bounds__(256) bc_kernel(const float* __restrict__ Xc,
                                                 const float* __restrict__ WB,
                                                 const float* __restrict__ WC,
                                                 float* __restrict__ Bo,
                                                 float* __restrict__ Co) {
    __shared__ float row[Dm];
    const int l = blockIdx.x;
    for (int k = threadIdx.x; k < Dm; k += 256) row[k] = Xc[(size_t)l * Dm + k];
    __syncthreads();
    const int part = threadIdx.x & 7;
    const int out = threadIdx.x >> 3;   // 0..31
    const int n = out & 15;
    const float* W = (out < 16) ? WB : WC;
    float s = 0.0f;
    for (int k = part; k < Dm; k += 8) s = fmaf(row[k], W[k * Ns + n], s);
#pragma unroll
    for (int off = 4; off; off >>= 1) s += __shfl_down_sync(0xffffffffu, s, off, 8);
    if (part == 0) {
        if (out < 16) Bo[l * Ns + n] = s;
        else          Co[l * Ns + n] = s;
    }
}

// ---------------- selective scan (emits split-bf16 y) ------------------------
__global__ void __launch_bounds__(128) scan_kernel(const float* __restrict__ delta,
                                                   const float* __restrict__ Xc,
                                                   const float* __restrict__ Bm,
                                                   const float* __restrict__ Cm,
                                                   const float* __restrict__ Alog,
                                                   bf16* __restrict__ Yhi,
                                                   bf16* __restrict__ Ylo) {
    const int n = threadIdx.x & 15;
    const int d = blockIdx.x * 8 + (threadIdx.x >> 4);
    const float a = -expf(Alog[d * Ns + n]);
    float h = 0.0f;
    for (int l = 0; l < Dm; l++) {
        float de = delta[(size_t)l * Dm + d];
        float xv = Xc[(size_t)l * Dm + d];
        float bv = Bm[l * Ns + n];
        float cv = Cm[l * Ns + n];
        float e = __expf(de * a);
        h = fmaf(e, h, de * xv * bv);
        float p = h * cv;
#pragma unroll
        for (int off = 8; off; off >>= 1) p += __shfl_down_sync(0xffffffffu, p, off, 16);
        if (n == 0) {
            bf16 hh = __float2bfloat16(p);
            size_t idx = (size_t)l * Dm + d;
            Yhi[idx] = hh;
            Ylo[idx] = __float2bfloat16(p - __bfloat162float(hh));
        }
    }
}

// ---------------- launch ------------------------------------------------------
extern "C" void kernel_launch(void* const* d_in, const int* in_sizes, int n_in,
                              void* d_out, int out_size) {
    const float* x    = (const float*)d_in[0];  // [2,1024,1024]
    const float* Wp   = (const float*)d_in[1];
    const float* bp   = (const float*)d_in[2];
    const float* cw   = (const float*)d_in[3];  // [1024,1024,3]
    const float* cb   = (const float*)d_in[4];
    const float* Alog = (const float*)d_in[5];
    const float* Wd   = (const float*)d_in[6];
    const float* WB   = (const float*)d_in[7];
    const float* WC   = (const float*)d_in[8];
    float* out = (float*)d_out;

    bf16 *xhi, *xlo, *Wphi, *Wplo, *cwhi, *cwlo, *WdThi, *WdTlo;
    bf16 *xghi, *xglo, *cBhi, *cBlo, *xchi, *xclo, *yhi, *ylo, *thi, *tlo;
    float *p0, *xc, *del, *Bm, *Cm;
    cudaGetSymbolAddress((void**)&xhi, g_xhi);   cudaGetSymbolAddress((void**)&xlo, g_xlo);
    cudaGetSymbolAddress((void**)&Wphi, g_Wphi); cudaGetSymbolAddress((void**)&Wplo, g_Wplo);
    cudaGetSymbolAddress((void**)&cwhi, g_cwhi); cudaGetSymbolAddress((void**)&cwlo, g_cwlo);
    cudaGetSymbolAddress((void**)&WdThi, g_WdThi); cudaGetSymbolAddress((void**)&WdTlo, g_WdTlo);
    cudaGetSymbolAddress((void**)&xghi, g_xghi); cudaGetSymbolAddress((void**)&xglo, g_xglo);
    cudaGetSymbolAddress((void**)&cBhi, g_cBhi); cudaGetSymbolAddress((void**)&cBlo, g_cBlo);
    cudaGetSymbolAddress((void**)&xchi, g_xchi); cudaGetSymbolAddress((void**)&xclo, g_xclo);
    cudaGetSymbolAddress((void**)&yhi, g_yhi);   cudaGetSymbolAddress((void**)&ylo, g_ylo);
    cudaGetSymbolAddress((void**)&thi, g_thi);   cudaGetSymbolAddress((void**)&tlo, g_tlo);
    cudaGetSymbolAddress((void**)&p0, g_p0);
    cudaGetSymbolAddress((void**)&xc, g_xc);
    cudaGetSymbolAddress((void**)&del, g_delta);
    cudaGetSymbolAddress((void**)&Bm, g_Bm);
    cudaGetSymbolAddress((void**)&Cm, g_Cm);

    const dim3 gg(Dm / 64, Dm / 128);   // (16, 8)

    // input splits
    split_k<<<(2 * Dm * Dm) / (256 * 4), 256>>>(x, xhi, xlo, 2 * Dm * Dm);
    split_k<<<(Dm * Dm) / (256 * 4), 256>>>(Wp, Wphi, Wplo, Dm * Dm);
    split_k<<<(Dm * KC) / (256 * 4), 256>>>(cw, cwhi, cwlo, Dm * KC);
    transpose_split_k<<<dim3(32, 32), dim3(32, 8)>>>(Wd, WdThi, WdTlo);

    // p0 = x0 @ Wp^T + b  (fp32 for conv-B build)
    gemm_bf3<1, false, true, false><<<gg, 256>>>(xhi, xlo, Wphi, Wplo, bp,
                                                 p0, nullptr, nullptr, Dm, Dm, Dm);
    // xg = silu(x1 @ Wp^T + b)  (split only; B operand of t-GEMM)
    gemm_bf3<2, false, false, true><<<gg, 256>>>(xhi + Dm * Dm, xlo + Dm * Dm, Wphi, Wplo, bp,
                                                 nullptr, xghi, xglo, Dm, Dm, Dm);
    // conv B matrix
    conv_b_build<<<dim3(32, 32), 256>>>(p0, cBhi, cBlo);
    // xc = silu(conv(xm) + cb)   [row bias]
    gemm_bf3<2, true, true, true><<<gg, 256>>>(cwhi, cwlo, cBhi, cBlo, cb,
                                               xc, xchi, xclo, Dm, Dm, KC);
    // delta = softplus(xc @ W_delta)
    gemm_bf3<3, false, true, false><<<gg, 256>>>(xchi, xclo, WdThi, WdTlo, nullptr,
                                                 del, nullptr, nullptr, Dm, Dm, Dm);
    // B, C projections
    bc_kernel<<<Dm, 256>>>(xc, WB, WC, Bm, Cm);
    // selective scan -> y (split)
    scan_kernel<<<Dm / 8, 128>>>(del, xc, Bm, Cm, Alog, yhi, ylo);
    // t = y @ xg^T  (split only)
    gemm_bf3<0, false, false, true><<<gg, 256>>>(yhi, ylo, xghi, xglo, nullptr,
                                                 nullptr, thi, tlo, Dm, Dm, Dm);
    // out = t @ Wp^T + b
    gemm_bf3<1, false, true, false><<<gg, 256>>>(thi, tlo, Wphi, Wplo, bp,
                                                 out, nullptr, nullptr, Dm, Dm, Dm);
}

// round 4
// speedup vs baseline: 2.2812x; 1.2084x over previous
#include <cuda_runtime.h>
#include <cuda_bf16.h>
#include <math.h>
#include <stdint.h>

constexpr int Dm = 1024;   // dim == seq len L
constexpr int Ns = 16;     // SSM state size
constexpr int KC = 3 * Dm; // conv GEMM K = 3072

typedef __nv_bfloat16 bf16;

// ---------------- scratch (static device globals: allocation-free) ----------
__device__ bf16 g_xhi[2 * Dm * Dm], g_xlo[2 * Dm * Dm];
__device__ bf16 g_Wphi[Dm * Dm],   g_Wplo[Dm * Dm];
__device__ bf16 g_cwhi[Dm * KC],   g_cwlo[Dm * KC];
__device__ bf16 g_WdThi[Dm * Dm],  g_WdTlo[Dm * Dm];
__device__ float g_p0[Dm * Dm];
__device__ bf16 g_xghi[Dm * Dm],   g_xglo[Dm * Dm];
__device__ bf16 g_cBhi[Dm * KC],   g_cBlo[Dm * KC];
__device__ float g_xc[Dm * Dm];
__device__ bf16 g_xchi[Dm * Dm],   g_xclo[Dm * Dm];
__device__ float g_delta[Dm * Dm];
__device__ float g_Bm[Dm * Ns], g_Cm[Dm * Ns];
__device__ bf16 g_yhi[Dm * Dm],    g_ylo[Dm * Dm];
__device__ bf16 g_thi[Dm * Dm],    g_tlo[Dm * Dm];

__device__ __forceinline__ float sigmoidf_(float x) {
    return 1.0f / (1.0f + expf(-x));
}

__device__ __forceinline__ uint32_t smem_u32(const void* p) {
    uint32_t a;
    asm("{ .reg .u64 t; cvta.to.shared.u64 t, %1; cvt.u32.u64 %0, t; }" : "=r"(a) : "l"(p));
    return a;
}

#define SWZ(x) ((x) ^ (((x) >> 3) & 0x70))

__device__ __forceinline__ void cpa16(uint32_t dst, const void* src) {
    asm volatile("cp.async.cg.shared.global [%0], [%1], 16;" :: "r"(dst), "l"(src));
}

#define MMA_BF16(c, a, b0, b1)                                                   \
    asm volatile(                                                                \
        "mma.sync.aligned.m16n8k16.row.col.f32.bf16.bf16.f32 "                   \
        "{%0,%1,%2,%3},{%4,%5,%6,%7},{%8,%9},{%0,%1,%2,%3};"                     \
        : "+f"(c[0]), "+f"(c[1]), "+f"(c[2]), "+f"(c[3])                         \
        : "r"(a[0]), "r"(a[1]), "r"(a[2]), "r"(a[3]), "r"(b0), "r"(b1))

#define LDSM_X4(r0, r1, r2, r3, addr)                                            \
    asm volatile("ldmatrix.sync.aligned.m8n8.x4.shared.b16 {%0,%1,%2,%3}, [%4];" \
        : "=r"(r0), "=r"(r1), "=r"(r2), "=r"(r3) : "r"(addr))

// ---------------- fp32 -> (hi,lo) bf16 split --------------------------------
__global__ void __launch_bounds__(256) split_k(const float* __restrict__ in,
                                               bf16* __restrict__ hi,
                                               bf16* __restrict__ lo, int n) {
    int i = (blockIdx.x * 256 + threadIdx.x) * 4;
    if (i >= n) return;
    float4 v = *(const float4*)(in + i);
    float vv[4] = {v.x, v.y, v.z, v.w};
#pragma unroll
    for (int j = 0; j < 4; j++) {
        bf16 h = __float2bfloat16(vv[j]);
        hi[i + j] = h;
        lo[i + j] = __float2bfloat16(vv[j] - __bfloat162float(h));
    }
}

// ---------------- transpose + split (for W_delta) ---------------------------
__global__ void __launch_bounds__(256) transpose_split_k(const float* __restrict__ In,
                                                         bf16* __restrict__ hi,
                                                         bf16* __restrict__ lo) {
    __shared__ float t[32][33];
    int x0 = blockIdx.x * 32, y0 = blockIdx.y * 32;
    int tx = threadIdx.x;
    for (int j = threadIdx.y; j < 32; j += 8)
        t[j][tx] = In[(y0 + j) * Dm + x0 + tx];
    __syncthreads();
    for (int j = threadIdx.y; j < 32; j += 8) {
        float v = t[tx][j];
        bf16 h = __float2bfloat16(v);
        size_t idx = (size_t)(x0 + j) * Dm + y0 + tx;
        hi[idx] = h;
        lo[idx] = __float2bfloat16(v - __bfloat162float(h));
    }
}

// ---------------- build conv B matrix: B[d, i*3+kk] = p0[i, d-1+kk] ----------
__global__ void __launch_bounds__(256) conv_b_build(const float* __restrict__ P0,
                                                    bf16* __restrict__ hi,
                                                    bf16* __restrict__ lo) {
    __shared__ float Xs[32][35];
    int d0 = blockIdx.x * 32, i0 = blockIdx.y * 32;
    int tid = threadIdx.x;
    for (int idx = tid; idx < 32 * 34; idx += 256) {
        int r = idx / 34, c = idx % 34;
        int gd = d0 - 1 + c;
        Xs[r][c] = (gd >= 0 && gd < Dm) ? P0[(size_t)(i0 + r) * Dm + gd] : 0.0f;
    }
    __syncthreads();
    int i = tid & 31;
    for (int dl = tid >> 5; dl < 32; dl += 8) {
        size_t base = (size_t)(d0 + dl) * KC + (size_t)(i0 + i) * 3;
#pragma unroll
        for (int kk = 0; kk < 3; kk++) {
            float x = Xs[i][dl + kk];
            bf16 h = __float2bfloat16(x);
            hi[base + kk] = h;
            lo[base + kk] = __float2bfloat16(x - __bfloat162float(h));
        }
    }
}

// ---------------- bf16-split HMMA GEMM with cp.async pipeline ----------------
// C[m,n] = sum_k A[m,k]*B[n,k]; A=Ah+Al, B=Bh+Bl; C ~= Ah*Bh + Ah*Bl + Al*Bh.
// CTA tile 128(M)x64(N), K-block 64, 3-stage cp.async pipeline, ldmatrix frags.
// Warp layout: 4(M) x 2(N), warp tile 32x32.
// Stage layout (48KB): AH[128][128B] | AL | BH[64][128B] | BL
constexpr int STAGE = 49152;
constexpr int OFF_AL = 16384, OFF_BH = 32768, OFF_BL = 40960;

template <int EPI, bool BIASROW, bool WF32, bool WSPLIT, bool DUAL>
__global__ void __launch_bounds__(256, 1)
gemm_mma(const bf16* __restrict__ Ah, const bf16* __restrict__ Al,
         const bf16* __restrict__ Bh, const bf16* __restrict__ Bl,
         const float* __restrict__ bias,
         float* __restrict__ Cf, bf16* __restrict__ Chi, bf16* __restrict__ Clo,
         int Nn, int K)
{
    extern __shared__ __align__(1024) char dyns[];
    const int tid = threadIdx.x;
    const int lane = tid & 31, warp = tid >> 5;
    const int m0 = blockIdx.y * 128, n0 = blockIdx.x * 64;
    const uint32_t dbase = smem_u32(dyns);
    const int S = K >> 6;

    float acc[2][4][4];
#pragma unroll
    for (int a = 0; a < 2; a++)
#pragma unroll
        for (int b = 0; b < 4; b++)
#pragma unroll
            for (int c = 0; c < 4; c++) acc[a][b][c] = 0.0f;

    auto load_stage = [&](int s) {
        const uint32_t sb = dbase + (s % 3) * STAGE;
        const int k0 = s << 6;
#pragma unroll
        for (int i = 0; i < 4; i++) {
            int q = tid + (i << 8);
            int r = q >> 3, c = q & 7;
            uint32_t so = SWZ((uint32_t)(r * 128 + c * 16));
            size_t ga = (size_t)(m0 + r) * K + k0 + c * 8;
            cpa16(sb + so, Ah + ga);
            cpa16(sb + OFF_AL + so, Al + ga);
        }
#pragma unroll
        for (int i = 0; i < 2; i++) {
            int q = tid + (i << 8);
            int r = q >> 3, c = q & 7;
            uint32_t so = SWZ((uint32_t)(r * 128 + c * 16));
            size_t gb = (size_t)(n0 + r) * K + k0 + c * 8;
            cpa16(sb + OFF_BH + so, Bh + gb);
            cpa16(sb + OFF_BL + so, Bl + gb);
        }
        asm volatile("cp.async.commit_group;" ::: "memory");
    };

    load_stage(0);
    load_stage(1);
    load_stage(2);

    const int wm = (warp & 3) * 32, wn = (warp >> 2) * 32;
    const uint32_t frow = (lane & 7) + ((lane >> 3) & 1) * 8;
    const uint32_t fxor = (frow & 7) << 4;
    const uint32_t fcol = (lane >> 4) << 4;

    for (int s = 0; s < S; s++) {
        asm volatile("cp.async.wait_group 2;" ::: "memory");
        __syncthreads();
        const uint32_t sb = dbase + (s % 3) * STAGE;
#pragma unroll
        for (int ks = 0; ks < 4; ks++) {
            const uint32_t kb = ks * 32;
            const uint32_t kc = (kb + fcol) ^ fxor;
            uint32_t ah[2][4], al[2][4], bh[2][4], bl[2][4];
#pragma unroll
            for (int mi = 0; mi < 2; mi++) {
                uint32_t ra = sb + (wm + mi * 16 + frow) * 128 + kc;
                LDSM_X4(ah[mi][0], ah[mi][1], ah[mi][2], ah[mi][3], ra);
                LDSM_X4(al[mi][0], al[mi][1], al[mi][2], al[mi][3], ra + OFF_AL);
            }
#pragma unroll
            for (int ni = 0; ni < 2; ni++) {
                uint32_t rb = sb + OFF_BH + (wn + ni * 16 + frow) * 128 + kc;
                LDSM_X4(bh[ni][0], bh[ni][1], bh[ni][2], bh[ni][3], rb);
                LDSM_X4(bl[ni][0], bl[ni][1], bl[ni][2], bl[ni][3], rb + 8192);
            }
#pragma unroll
            for (int mi = 0; mi < 2; mi++)
#pragma unroll
                for (int nj = 0; nj < 4; nj++) {
                    const int t = nj >> 1, h = nj & 1;
                    MMA_BF16(acc[mi][nj], ah[mi], bh[t][h], bh[t][h + 2]);
                    MMA_BF16(acc[mi][nj], ah[mi], bl[t][h], bl[t][h + 2]);
                    MMA_BF16(acc[mi][nj], al[mi], bh[t][h], bh[t][h + 2]);
                }
        }
        __syncthreads();
        if (s + 3 < S) load_stage(s + 3);
        else asm volatile("cp.async.commit_group;" ::: "memory");
    }

    // ---------------- epilogue ------------------------------------------------
    const int gr = lane >> 2, gc = lane & 3;
    const bool second = DUAL && (m0 >= Dm);
#pragma unroll
    for (int mi = 0; mi < 2; mi++) {
#pragma unroll
        for (int half = 0; half < 2; half++) {
            const int m = m0 + wm + mi * 16 + gr + half * 8;
            const int mrow = second ? (m - Dm) : m;
            float bm = 0.0f;
            if ((EPI == 1 || EPI == 2) && BIASROW) bm = bias[m];
#pragma unroll
            for (int nj = 0; nj < 4; nj++) {
                const int n = n0 + wn + nj * 8 + 2 * gc;
                float v0 = acc[mi][nj][half * 2 + 0];
                float v1 = acc[mi][nj][half * 2 + 1];
                if (EPI == 1 || EPI == 2) {
                    if (BIASROW) { v0 += bm; v1 += bm; }
                    else         { v0 += bias[n]; v1 += bias[n + 1]; }
                }
                if (EPI == 2 || (DUAL && second)) {
                    v0 *= sigmoidf_(v0); v1 *= sigmoidf_(v1);
                }
                if (EPI == 3) {
                    v0 = fmaxf(v0, 0.0f) + log1pf(expf(-fabsf(v0)));
                    v1 = fmaxf(v1, 0.0f) + log1pf(expf(-fabsf(v1)));
                }
                size_t idx = (size_t)mrow * Nn + n;
                const bool wf = WF32 && !(DUAL && second);
                const bool ws = (WSPLIT && !DUAL) || (DUAL && second);
                if (wf) *(float2*)&Cf[idx] = make_float2(v0, v1);
                if (ws) {
                    bf16 h0 = __float2bfloat16(v0);
                    bf16 h1 = __float2bfloat16(v1);
                    __nv_bfloat162 hh; hh.x = h0; hh.y = h1;
                    __nv_bfloat162 ll;
                    ll.x = __float2bfloat16(v0 - __bfloat162float(h0));
                    ll.y = __float2bfloat16(v1 - __bfloat162float(h1));
                    *(__nv_bfloat162*)&Chi[idx] = hh;
                    *(__nv_bfloat162*)&Clo[idx] = ll;
                }
            }
        }
    }
}

// ---------------- B/C projections: [L,D] @ [D,16] ---------------------------
__global__ void __launch_bounds__(256) bc_kernel(const float* __restrict__ Xc,
                                                 const float* __restrict__ WB,
                                                 const float* __restrict__ WC,
                                                 float* __restrict__ Bo,
                                                 float* __restrict__ Co) {
    __shared__ float row[Dm];
    const int l = blockIdx.x;
    for (int k = threadIdx.x; k < Dm; k += 256) row[k] = Xc[(size_t)l * Dm + k];
    __syncthreads();
    const int part = threadIdx.x & 7;
    const int out = threadIdx.x >> 3;   // 0..31
    const int n = out & 15;
    const float* W = (out < 16) ? WB : WC;
    float s = 0.0f;
    for (int k = part; k < Dm; k += 8) s = fmaf(row[k], W[k * Ns + n], s);
#pragma unroll
    for (int off = 4; off; off >>= 1) s += __shfl_down_sync(0xffffffffu, s, off, 8);
    if (part == 0) {
        if (out < 16) Bo[l * Ns + n] = s;
        else          Co[l * Ns + n] = s;
    }
}

// ---------------- selective scan (emits split-bf16 y) ------------------------
__global__ void __launch_bounds__(128) scan_kernel(const float* __restrict__ delta,
                                                   const float* __restrict__ Xc,
                                                   const float* __restrict__ Bm,
                                                   const float* __restrict__ Cm,
                                                   const float* __restrict__ Alog,
                                                   bf16* __restrict__ Yhi,
                                                   bf16* __restrict__ Ylo) {
    const int n = threadIdx.x & 15;
    const int d = blockIdx.x * 8 + (threadIdx.x >> 4);
    const float a = -expf(Alog[d * Ns + n]);
    float h = 0.0f;
    for (int l = 0; l < Dm; l++) {
        float de = delta[(size_t)l * Dm + d];
        float xv = Xc[(size_t)l * Dm + d];
        float bv = Bm[l * Ns + n];
        float cv = Cm[l * Ns + n];
        float e = __expf(de * a);
        h = fmaf(e, h, de * xv * bv);
        float p = h * cv;
#pragma unroll
        for (int off = 8; off; off >>= 1) p += __shfl_down_sync(0xffffffffu, p, off, 16);
        if (n == 0) {
            bf16 hh = __float2bfloat16(p);
            size_t idx = (size_t)l * Dm + d;
            Yhi[idx] = hh;
            Ylo[idx] = __float2bfloat16(p - __bfloat162float(hh));
        }
    }
}

// ---------------- launch ------------------------------------------------------
extern "C" void kernel_launch(void* const* d_in, const int* in_sizes, int n_in,
                              void* d_out, int out_size) {
    const float* x    = (const float*)d_in[0];
    const float* Wp   = (const float*)d_in[1];
    const float* bp   = (const float*)d_in[2];
    const float* cw   = (const float*)d_in[3];
    const float* cb   = (const float*)d_in[4];
    const float* Alog = (const float*)d_in[5];
    const float* Wd   = (const float*)d_in[6];
    const float* WB   = (const float*)d_in[7];
    const float* WC   = (const float*)d_in[8];
    float* out = (float*)d_out;

    bf16 *xhi, *xlo, *Wphi, *Wplo, *cwhi, *cwlo, *WdThi, *WdTlo;
    bf16 *xghi, *xglo, *cBhi, *cBlo, *xchi, *xclo, *yhi, *ylo, *thi, *tlo;
    float *p0, *xc, *del, *Bm, *Cm;
    cudaGetSymbolAddress((void**)&xhi, g_xhi);   cudaGetSymbolAddress((void**)&xlo, g_xlo);
    cudaGetSymbolAddress((void**)&Wphi, g_Wphi); cudaGetSymbolAddress((void**)&Wplo, g_Wplo);
    cudaGetSymbolAddress((void**)&cwhi, g_cwhi); cudaGetSymbolAddress((void**)&cwlo, g_cwlo);
    cudaGetSymbolAddress((void**)&WdThi, g_WdThi); cudaGetSymbolAddress((void**)&WdTlo, g_WdTlo);
    cudaGetSymbolAddress((void**)&xghi, g_xghi); cudaGetSymbolAddress((void**)&xglo, g_xglo);
    cudaGetSymbolAddress((void**)&cBhi, g_cBhi); cudaGetSymbolAddress((void**)&cBlo, g_cBlo);
    cudaGetSymbolAddress((void**)&xchi, g_xchi); cudaGetSymbolAddress((void**)&xclo, g_xclo);
    cudaGetSymbolAddress((void**)&yhi, g_yhi);   cudaGetSymbolAddress((void**)&ylo, g_ylo);
    cudaGetSymbolAddress((void**)&thi, g_thi);   cudaGetSymbolAddress((void**)&tlo, g_tlo);
    cudaGetSymbolAddress((void**)&p0, g_p0);
    cudaGetSymbolAddress((void**)&xc, g_xc);
    cudaGetSymbolAddress((void**)&del, g_delta);
    cudaGetSymbolAddress((void**)&Bm, g_Bm);
    cudaGetSymbolAddress((void**)&Cm, g_Cm);

    const int SMEM = 3 * STAGE;   // 147456
    cudaFuncSetAttribute(gemm_mma<1, false, true,  true,  true>,  cudaFuncAttributeMaxDynamicSharedMemorySize, SMEM);
    cudaFuncSetAttribute(gemm_mma<2, true,  true,  true,  false>, cudaFuncAttributeMaxDynamicSharedMemorySize, SMEM);
    cudaFuncSetAttribute(gemm_mma<3, false, true,  false, false>, cudaFuncAttributeMaxDynamicSharedMemorySize, SMEM);
    cudaFuncSetAttribute(gemm_mma<0, false, false, true,  false>, cudaFuncAttributeMaxDynamicSharedMemorySize, SMEM);
    cudaFuncSetAttribute(gemm_mma<1, false, true,  false, false>, cudaFuncAttributeMaxDynamicSharedMemorySize, SMEM);

    // splits
    split_k<<<(2 * Dm * Dm) / 1024, 256>>>(x, xhi, xlo, 2 * Dm * Dm);
    split_k<<<(Dm * Dm) / 1024, 256>>>(Wp, Wphi, Wplo, Dm * Dm);
    split_k<<<(Dm * KC) / 1024, 256>>>(cw, cwhi, cwlo, Dm * KC);
    transpose_split_k<<<dim3(32, 32), dim3(32, 8)>>>(Wd, WdThi, WdTlo);

    // fused input projections: rows <1024 -> p0 (f32,+bias); >=1024 -> xg (silu,split)
    gemm_mma<1, false, true, true, true><<<dim3(16, 16), 256, SMEM>>>(
        xhi, xlo, Wphi, Wplo, bp, p0, xghi, xglo, Dm, Dm);

    // conv as GEMM (K = 3072)
    conv_b_build<<<dim3(32, 32), 256>>>(p0, cBhi, cBlo);
    gemm_mma<2, true, true, true, false><<<dim3(16, 8), 256, SMEM>>>(
        cwhi, cwlo, cBhi, cBlo, cb, xc, xchi, xclo, Dm, KC);

    // delta = softplus(xc @ W_delta)
    gemm_mma<3, false, true, false, false><<<dim3(16, 8), 256, SMEM>>>(
        xchi, xclo, WdThi, WdTlo, nullptr, del, nullptr, nullptr, Dm, Dm);

    // B, C projections + scan
    bc_kernel<<<Dm, 256>>>(xc, WB, WC, Bm, Cm);
    scan_kernel<<<Dm / 8, 128>>>(del, xc, Bm, Cm, Alog, yhi, ylo);

    // t = y @ xg^T
    gemm_mma<0, false, false, true, false><<<dim3(16, 8), 256, SMEM>>>(
        yhi, ylo, xghi, xglo, nullptr, nullptr, thi, tlo, Dm, Dm);

    // out = t @ Wp^T + b
    gemm_mma<1, false, true, false, false><<<dim3(16, 8), 256, SMEM>>>(
        thi, tlo, Wphi, Wplo, bp, out, nullptr, nullptr, Dm, Dm);
}

// round 5
// speedup vs baseline: 2.3149x; 1.0148x over previous
#include <cuda_runtime.h>
#include <cuda_bf16.h>
#include <math.h>
#include <stdint.h>

constexpr int Dm = 1024;   // dim == seq len L
constexpr int Ns = 16;     // SSM state size
constexpr int KC = 3 * Dm; // conv GEMM K = 3072

typedef __nv_bfloat16 bf16;

// ---------------- scratch (static device globals: allocation-free) ----------
__device__ bf16 g_xhi[2 * Dm * Dm], g_xlo[2 * Dm * Dm];
__device__ bf16 g_Wphi[Dm * Dm],   g_Wplo[Dm * Dm];
__device__ bf16 g_cwhi[Dm * KC],   g_cwlo[Dm * KC];
__device__ bf16 g_WdThi[Dm * Dm],  g_WdTlo[Dm * Dm];
__device__ float g_p0[Dm * Dm];
__device__ bf16 g_xghi[Dm * Dm],   g_xglo[Dm * Dm];
__device__ bf16 g_cBhi[Dm * KC],   g_cBlo[Dm * KC];
__device__ float g_xc[Dm * Dm];
__device__ bf16 g_xchi[Dm * Dm],   g_xclo[Dm * Dm];
__device__ float g_delta[Dm * Dm];
__device__ float g_Bm[Dm * Ns], g_Cm[Dm * Ns];
__device__ bf16 g_yhi[Dm * Dm],    g_ylo[Dm * Dm];
__device__ bf16 g_thi[Dm * Dm],    g_tlo[Dm * Dm];

__device__ __forceinline__ float sigmoidf_(float x) {
    return 1.0f / (1.0f + expf(-x));
}

__device__ __forceinline__ uint32_t smem_u32(const void* p) {
    uint32_t a;
    asm("{ .reg .u64 t; cvta.to.shared.u64 t, %1; cvt.u32.u64 %0, t; }" : "=r"(a) : "l"(p));
    return a;
}

#define SWZ(x) ((x) ^ (((x) >> 3) & 0x70))

__device__ __forceinline__ void cpa16(uint32_t dst, const void* src) {
    asm volatile("cp.async.cg.shared.global [%0], [%1], 16;" :: "r"(dst), "l"(src));
}

#define MMA_BF16(c, a, b0, b1)                                                   \
    asm volatile(                                                                \
        "mma.sync.aligned.m16n8k16.row.col.f32.bf16.bf16.f32 "                   \
        "{%0,%1,%2,%3},{%4,%5,%6,%7},{%8,%9},{%0,%1,%2,%3};"                     \
        : "+f"(c[0]), "+f"(c[1]), "+f"(c[2]), "+f"(c[3])                         \
        : "r"(a[0]), "r"(a[1]), "r"(a[2]), "r"(a[3]), "r"(b0), "r"(b1))

#define LDSM_X4(r0, r1, r2, r3, addr)                                            \
    asm volatile("ldmatrix.sync.aligned.m8n8.x4.shared.b16 {%0,%1,%2,%3}, [%4];" \
        : "=r"(r0), "=r"(r1), "=r"(r2), "=r"(r3) : "r"(addr))

// ---------------- fp32 -> (hi,lo) bf16 split --------------------------------
__global__ void __launch_bounds__(256) split_k(const float* __restrict__ in,
                                               bf16* __restrict__ hi,
                                               bf16* __restrict__ lo, int n) {
    int i = (blockIdx.x * 256 + threadIdx.x) * 4;
    if (i >= n) return;
    float4 v = *(const float4*)(in + i);
    float vv[4] = {v.x, v.y, v.z, v.w};
#pragma unroll
    for (int j = 0; j < 4; j++) {
        bf16 h = __float2bfloat16(vv[j]);
        hi[i + j] = h;
        lo[i + j] = __float2bfloat16(vv[j] - __bfloat162float(h));
    }
}

// ---------------- transpose + split (for W_delta) ---------------------------
__global__ void __launch_bounds__(256) transpose_split_k(const float* __restrict__ In,
                                                         bf16* __restrict__ hi,
                                                         bf16* __restrict__ lo) {
    __shared__ float t[32][33];
    int x0 = blockIdx.x * 32, y0 = blockIdx.y * 32;
    int tx = threadIdx.x;
    for (int j = threadIdx.y; j < 32; j += 8)
        t[j][tx] = In[(y0 + j) * Dm + x0 + tx];
    __syncthreads();
    for (int j = threadIdx.y; j < 32; j += 8) {
        float v = t[tx][j];
        bf16 h = __float2bfloat16(v);
        size_t idx = (size_t)(x0 + j) * Dm + y0 + tx;
        hi[idx] = h;
        lo[idx] = __float2bfloat16(v - __bfloat162float(h));
    }
}

// ---------------- build conv B matrix: B[d, i*3+kk] = p0[i, d-1+kk] ----------
__global__ void __launch_bounds__(256) conv_b_build(const float* __restrict__ P0,
                                                    bf16* __restrict__ hi,
                                                    bf16* __restrict__ lo) {
    __shared__ float Xs[32][35];
    int d0 = blockIdx.x * 32, i0 = blockIdx.y * 32;
    int tid = threadIdx.x;
    for (int idx = tid; idx < 32 * 34; idx += 256) {
        int r = idx / 34, c = idx % 34;
        int gd = d0 - 1 + c;
        Xs[r][c] = (gd >= 0 && gd < Dm) ? P0[(size_t)(i0 + r) * Dm + gd] : 0.0f;
    }
    __syncthreads();
    int i = tid & 31;
    for (int dl = tid >> 5; dl < 32; dl += 8) {
        size_t base = (size_t)(d0 + dl) * KC + (size_t)(i0 + i) * 3;
#pragma unroll
        for (int kk = 0; kk < 3; kk++) {
            float x = Xs[i][dl + kk];
            bf16 h = __float2bfloat16(x);
            hi[base + kk] = h;
            lo[base + kk] = __float2bfloat16(x - __bfloat162float(h));
        }
    }
}

// ---------------- bf16-split HMMA GEMM, cp.async pipeline, frag prefetch -----
// C[m,n] = sum_k A[m,k]*B[n,k]; A=Ah+Al, B=Bh+Bl; C ~= Ah*Bh + Ah*Bl + Al*Bh.
// CTA tile 128(M) x TN(N), K-block 64, 3-stage cp.async pipeline.
// Warps 4(M) x 2(N): warp tile 32 x TN/2.
template <int TN, int EPI, bool BIASROW, bool WF32, bool WSPLIT, bool DUAL>
__global__ void __launch_bounds__(256, 1)
gemm_mma(const bf16* __restrict__ Ah, const bf16* __restrict__ Al,
         const bf16* __restrict__ Bh, const bf16* __restrict__ Bl,
         const float* __restrict__ bias,
         float* __restrict__ Cf, bf16* __restrict__ Chi, bf16* __restrict__ Clo,
         int Nn, int K)
{
    constexpr int OFF_AL = 16384;
    constexpr int OFF_BH = 32768;
    constexpr int BHL = TN * 128;          // bytes of one B buffer
    constexpr int STAGEB = 32768 + TN * 256;
    constexpr int WN = TN / 2;             // warp n-tile
    constexpr int NG = WN / 16;            // ldmatrix groups per warp (B)
    constexpr int NJ = WN / 8;             // 8-wide acc tiles per warp

    extern __shared__ __align__(1024) char dyns[];
    const int tid = threadIdx.x;
    const int lane = tid & 31, warp = tid >> 5;
    const int m0 = blockIdx.y * 128, n0 = blockIdx.x * TN;
    const uint32_t dbase = smem_u32(dyns);
    const int S = K >> 6;

    float acc[2][NJ][4];
#pragma unroll
    for (int a = 0; a < 2; a++)
#pragma unroll
        for (int b = 0; b < NJ; b++)
#pragma unroll
            for (int c = 0; c < 4; c++) acc[a][b][c] = 0.0f;

    auto load_stage = [&](int s) {
        const uint32_t sb = dbase + (s % 3) * STAGEB;
        const int k0 = s << 6;
#pragma unroll
        for (int i = 0; i < 4; i++) {
            int q = tid + (i << 8);
            int r = q >> 3, c = q & 7;
            uint32_t so = SWZ((uint32_t)(r * 128 + c * 16));
            size_t ga = (size_t)(m0 + r) * K + k0 + c * 8;
            cpa16(sb + so, Ah + ga);
            cpa16(sb + OFF_AL + so, Al + ga);
        }
#pragma unroll
        for (int i = 0; i < TN / 32; i++) {
            int q = tid + (i << 8);
            int r = q >> 3, c = q & 7;
            uint32_t so = SWZ((uint32_t)(r * 128 + c * 16));
            size_t gb = (size_t)(n0 + r) * K + k0 + c * 8;
            cpa16(sb + OFF_BH + so, Bh + gb);
            cpa16(sb + OFF_BH + BHL + so, Bl + gb);
        }
        asm volatile("cp.async.commit_group;" ::: "memory");
    };

    load_stage(0);
    load_stage(1);
    load_stage(2);

    const int wm = (warp & 3) * 32, wn = (warp >> 2) * WN;
    const uint32_t frow = (lane & 7) + ((lane >> 3) & 1) * 8;
    const uint32_t fxor = (frow & 7) << 4;
    const uint32_t fcol = (lane >> 4) << 4;

    // fragment load helper
    auto ldfrag = [&](uint32_t (&A0)[2][4], uint32_t (&A1)[2][4],
                      uint32_t (&B0)[NG][4], uint32_t (&B1)[NG][4],
                      uint32_t sb, int ks) {
        const uint32_t kc = (uint32_t)(ks * 32 + fcol) ^ fxor;
#pragma unroll
        for (int mi = 0; mi < 2; mi++) {
            uint32_t ra = sb + (wm + mi * 16 + frow) * 128 + kc;
            LDSM_X4(A0[mi][0], A0[mi][1], A0[mi][2], A0[mi][3], ra);
            LDSM_X4(A1[mi][0], A1[mi][1], A1[mi][2], A1[mi][3], ra + OFF_AL);
        }
#pragma unroll
        for (int ni = 0; ni < NG; ni++) {
            uint32_t rb = sb + OFF_BH + (wn + ni * 16 + frow) * 128 + kc;
            LDSM_X4(B0[ni][0], B0[ni][1], B0[ni][2], B0[ni][3], rb);
            LDSM_X4(B1[ni][0], B1[ni][1], B1[ni][2], B1[ni][3], rb + BHL);
        }
    };
    // term-major MMA on a fragment set
    auto do_mma = [&](uint32_t (&A0)[2][4], uint32_t (&A1)[2][4],
                      uint32_t (&B0)[NG][4], uint32_t (&B1)[NG][4]) {
#pragma unroll
        for (int mi = 0; mi < 2; mi++)
#pragma unroll
            for (int nj = 0; nj < NJ; nj++)
                MMA_BF16(acc[mi][nj], A0[mi], B0[nj >> 1][nj & 1], B0[nj >> 1][(nj & 1) + 2]);
#pragma unroll
        for (int mi = 0; mi < 2; mi++)
#pragma unroll
            for (int nj = 0; nj < NJ; nj++)
                MMA_BF16(acc[mi][nj], A0[mi], B1[nj >> 1][nj & 1], B1[nj >> 1][(nj & 1) + 2]);
#pragma unroll
        for (int mi = 0; mi < 2; mi++)
#pragma unroll
            for (int nj = 0; nj < NJ; nj++)
                MMA_BF16(acc[mi][nj], A1[mi], B0[nj >> 1][nj & 1], B0[nj >> 1][(nj & 1) + 2]);
    };

    if constexpr (TN == 64) {
        // double-buffered fragments: prefetch ks+1 while computing ks
        uint32_t ahb[2][2][4], alb[2][2][4], bhb[2][NG][4], blb[2][NG][4];
        for (int s = 0; s < S; s++) {
            asm volatile("cp.async.wait_group 2;" ::: "memory");
            __syncthreads();
            const uint32_t sb = dbase + (s % 3) * STAGEB;
            ldfrag(ahb[0], alb[0], bhb[0], blb[0], sb, 0);
#pragma unroll
            for (int ks = 0; ks < 4; ks++) {
                const int cur = ks & 1, nxt = cur ^ 1;
                if (ks < 3) ldfrag(ahb[nxt], alb[nxt], bhb[nxt], blb[nxt], sb, ks + 1);
                do_mma(ahb[cur], alb[cur], bhb[cur], blb[cur]);
            }
            __syncthreads();
            if (s + 3 < S) load_stage(s + 3);
            else asm volatile("cp.async.commit_group;" ::: "memory");
        }
    } else {
        // single-buffered (48 MMA per 12 LDSM already hides latency)
        uint32_t ahb[2][4], alb[2][4], bhb[NG][4], blb[NG][4];
        for (int s = 0; s < S; s++) {
            asm volatile("cp.async.wait_group 2;" ::: "memory");
            __syncthreads();
            const uint32_t sb = dbase + (s % 3) * STAGEB;
#pragma unroll
            for (int ks = 0; ks < 4; ks++) {
                ldfrag(ahb, alb, bhb, blb, sb, ks);
                do_mma(ahb, alb, bhb, blb);
            }
            __syncthreads();
            if (s + 3 < S) load_stage(s + 3);
            else asm volatile("cp.async.commit_group;" ::: "memory");
        }
    }

    // ---------------- epilogue ------------------------------------------------
    const int gr = lane >> 2, gc = lane & 3;
    const bool second = DUAL && (m0 >= Dm);
#pragma unroll
    for (int mi = 0; mi < 2; mi++) {
#pragma unroll
        for (int half = 0; half < 2; half++) {
            const int m = m0 + wm + mi * 16 + gr + half * 8;
            const int mrow = second ? (m - Dm) : m;
            float bm = 0.0f;
            if ((EPI == 1 || EPI == 2) && BIASROW) bm = bias[m];
#pragma unroll
            for (int nj = 0; nj < NJ; nj++) {
                const int n = n0 + wn + nj * 8 + 2 * gc;
                float v0 = acc[mi][nj][half * 2 + 0];
                float v1 = acc[mi][nj][half * 2 + 1];
                if (EPI == 1 || EPI == 2) {
                    if (BIASROW) { v0 += bm; v1 += bm; }
                    else         { v0 += bias[n]; v1 += bias[n + 1]; }
                }
                if (EPI == 2 || (DUAL && second)) {
                    v0 *= sigmoidf_(v0); v1 *= sigmoidf_(v1);
                }
                if (EPI == 3) {
                    v0 = fmaxf(v0, 0.0f) + log1pf(expf(-fabsf(v0)));
                    v1 = fmaxf(v1, 0.0f) + log1pf(expf(-fabsf(v1)));
                }
                size_t idx = (size_t)mrow * Nn + n;
                const bool wf = WF32 && !(DUAL && second);
                const bool ws = (WSPLIT && !DUAL) || (DUAL && second);
                if (wf) *(float2*)&Cf[idx] = make_float2(v0, v1);
                if (ws) {
                    bf16 h0 = __float2bfloat16(v0);
                    bf16 h1 = __float2bfloat16(v1);
                    __nv_bfloat162 hh; hh.x = h0; hh.y = h1;
                    __nv_bfloat162 ll;
                    ll.x = __float2bfloat16(v0 - __bfloat162float(h0));
                    ll.y = __float2bfloat16(v1 - __bfloat162float(h1));
                    *(__nv_bfloat162*)&Chi[idx] = hh;
                    *(__nv_bfloat162*)&Clo[idx] = ll;
                }
            }
        }
    }
}

// ---------------- B/C projections: [L,D] @ [D,16] ---------------------------
__global__ void __launch_bounds__(256) bc_kernel(const float* __restrict__ Xc,
                                                 const float* __restrict__ WB,
                                                 const float* __restrict__ WC,
                                                 float* __restrict__ Bo,
                                                 float* __restrict__ Co) {
    __shared__ float row[Dm];
    const int l = blockIdx.x;
    for (int k = threadIdx.x; k < Dm; k += 256) row[k] = Xc[(size_t)l * Dm + k];
    __syncthreads();
    const int part = threadIdx.x & 7;
    const int out = threadIdx.x >> 3;   // 0..31
    const int n = out & 15;
    const float* W = (out < 16) ? WB : WC;
    float s = 0.0f;
    for (int k = part; k < Dm; k += 8) s = fmaf(row[k], W[k * Ns + n], s);
#pragma unroll
    for (int off = 4; off; off >>= 1) s += __shfl_down_sync(0xffffffffu, s, off, 8);
    if (part == 0) {
        if (out < 16) Bo[l * Ns + n] = s;
        else          Co[l * Ns + n] = s;
    }
}

// ---------------- selective scan (emits split-bf16 y) ------------------------
__global__ void __launch_bounds__(128) scan_kernel(const float* __restrict__ delta,
                                                   const float* __restrict__ Xc,
                                                   const float* __restrict__ Bm,
                                                   const float* __restrict__ Cm,
                                                   const float* __restrict__ Alog,
                                                   bf16* __restrict__ Yhi,
                                                   bf16* __restrict__ Ylo) {
    const int n = threadIdx.x & 15;
    const int d = blockIdx.x * 8 + (threadIdx.x >> 4);
    const float a = -expf(Alog[d * Ns + n]);
    float h = 0.0f;
    for (int l = 0; l < Dm; l++) {
        float de = delta[(size_t)l * Dm + d];
        float xv = Xc[(size_t)l * Dm + d];
        float bv = Bm[l * Ns + n];
        float cv = Cm[l * Ns + n];
        float e = __expf(de * a);
        h = fmaf(e, h, de * xv * bv);
        float p = h * cv;
#pragma unroll
        for (int off = 8; off; off >>= 1) p += __shfl_down_sync(0xffffffffu, p, off, 16);
        if (n == 0) {
            bf16 hh = __float2bfloat16(p);
            size_t idx = (size_t)l * Dm + d;
            Yhi[idx] = hh;
            Ylo[idx] = __float2bfloat16(p - __bfloat162float(hh));
        }
    }
}

// ---------------- launch ------------------------------------------------------
extern "C" void kernel_launch(void* const* d_in, const int* in_sizes, int n_in,
                              void* d_out, int out_size) {
    const float* x    = (const float*)d_in[0];
    const float* Wp   = (const float*)d_in[1];
    const float* bp   = (const float*)d_in[2];
    const float* cw   = (const float*)d_in[3];
    const float* cb   = (const float*)d_in[4];
    const float* Alog = (const float*)d_in[5];
    const float* Wd   = (const float*)d_in[6];
    const float* WB   = (const float*)d_in[7];
    const float* WC   = (const float*)d_in[8];
    float* out = (float*)d_out;

    bf16 *xhi, *xlo, *Wphi, *Wplo, *cwhi, *cwlo, *WdThi, *WdTlo;
    bf16 *xghi, *xglo, *cBhi, *cBlo, *xchi, *xclo, *yhi, *ylo, *thi, *tlo;
    float *p0, *xc, *del, *Bm, *Cm;
    cudaGetSymbolAddress((void**)&xhi, g_xhi);   cudaGetSymbolAddress((void**)&xlo, g_xlo);
    cudaGetSymbolAddress((void**)&Wphi, g_Wphi); cudaGetSymbolAddress((void**)&Wplo, g_Wplo);
    cudaGetSymbolAddress((void**)&cwhi, g_cwhi); cudaGetSymbolAddress((void**)&cwlo, g_cwlo);
    cudaGetSymbolAddress((void**)&WdThi, g_WdThi); cudaGetSymbolAddress((void**)&WdTlo, g_WdTlo);
    cudaGetSymbolAddress((void**)&xghi, g_xghi); cudaGetSymbolAddress((void**)&xglo, g_xglo);
    cudaGetSymbolAddress((void**)&cBhi, g_cBhi); cudaGetSymbolAddress((void**)&cBlo, g_cBlo);
    cudaGetSymbolAddress((void**)&xchi, g_xchi); cudaGetSymbolAddress((void**)&xclo, g_xclo);
    cudaGetSymbolAddress((void**)&yhi, g_yhi);   cudaGetSymbolAddress((void**)&ylo, g_ylo);
    cudaGetSymbolAddress((void**)&thi, g_thi);   cudaGetSymbolAddress((void**)&tlo, g_tlo);
    cudaGetSymbolAddress((void**)&p0, g_p0);
    cudaGetSymbolAddress((void**)&xc, g_xc);
    cudaGetSymbolAddress((void**)&del, g_delta);
    cudaGetSymbolAddress((void**)&Bm, g_Bm);
    cudaGetSymbolAddress((void**)&Cm, g_Cm);

    const int SMEM64  = 3 * (32768 + 64 * 256);   // 147456
    const int SMEM128 = 3 * (32768 + 128 * 256);  // 196608
    cudaFuncSetAttribute(gemm_mma<128, 1, false, true,  true,  true>,  cudaFuncAttributeMaxDynamicSharedMemorySize, SMEM128);
    cudaFuncSetAttribute(gemm_mma<64,  2, true,  true,  true,  false>, cudaFuncAttributeMaxDynamicSharedMemorySize, SMEM64);
    cudaFuncSetAttribute(gemm_mma<64,  3, false, true,  false, false>, cudaFuncAttributeMaxDynamicSharedMemorySize, SMEM64);
    cudaFuncSetAttribute(gemm_mma<64,  0, false, false, true,  false>, cudaFuncAttributeMaxDynamicSharedMemorySize, SMEM64);
    cudaFuncSetAttribute(gemm_mma<64,  1, false, true,  false, false>, cudaFuncAttributeMaxDynamicSharedMemorySize, SMEM64);

    // splits
    split_k<<<(2 * Dm * Dm) / 1024, 256>>>(x, xhi, xlo, 2 * Dm * Dm);
    split_k<<<(Dm * Dm) / 1024, 256>>>(Wp, Wphi, Wplo, Dm * Dm);
    split_k<<<(Dm * KC) / 1024, 256>>>(cw, cwhi, cwlo, Dm * KC);
    transpose_split_k<<<dim3(32, 32), dim3(32, 8)>>>(Wd, WdThi, WdTlo);

    // fused input projections (M=2048, tile 128x128, grid 128 = 1 wave):
    // rows <1024 -> p0 (f32,+bias); >=1024 -> xg (silu,split)
    gemm_mma<128, 1, false, true, true, true><<<dim3(8, 16), 256, SMEM128>>>(
        xhi, xlo, Wphi, Wplo, bp, p0, xghi, xglo, Dm, Dm);

    // conv as GEMM (K = 3072)
    conv_b_build<<<dim3(32, 32), 256>>>(p0, cBhi, cBlo);
    gemm_mma<64, 2, true, true, true, false><<<dim3(16, 8), 256, SMEM64>>>(
        cwhi, cwlo, cBhi, cBlo, cb, xc, xchi, xclo, Dm, KC);

    // delta = softplus(xc @ W_delta)
    gemm_mma<64, 3, false, true, false, false><<<dim3(16, 8), 256, SMEM64>>>(
        xchi, xclo, WdThi, WdTlo, nullptr, del, nullptr, nullptr, Dm, Dm);

    // B, C projections + scan
    bc_kernel<<<Dm, 256>>>(xc, WB, WC, Bm, Cm);
    scan_kernel<<<Dm / 8, 128>>>(del, xc, Bm, Cm, Alog, yhi, ylo);

    // t = y @ xg^T
    gemm_mma<64, 0, false, false, true, false><<<dim3(16, 8), 256, SMEM64>>>(
        yhi, ylo, xghi, xglo, nullptr, nullptr, thi, tlo, Dm, Dm);

    // out = t @ Wp^T + b
    gemm_mma<64, 1, false, true, false, false><<<dim3(16, 8), 256, SMEM64>>>(
        thi, tlo, Wphi, Wplo, bp, out, nullptr, nullptr, Dm, Dm);
}

// round 6
// speedup vs baseline: 2.3603x; 1.0196x over previous
#include <cuda_runtime.h>
#include <cuda_bf16.h>
#include <math.h>
#include <stdint.h>

constexpr int Dm = 1024;   // dim == seq len L
constexpr int Ns = 16;     // SSM state size
constexpr int KC = 3 * Dm; // conv GEMM K = 3072

typedef __nv_bfloat16 bf16;

// ---------------- scratch (static device globals: allocation-free) ----------
__device__ bf16 g_xhi[2 * Dm * Dm], g_xlo[2 * Dm * Dm];
__device__ bf16 g_Wphi[Dm * Dm],   g_Wplo[Dm * Dm];
__device__ bf16 g_cwhi[Dm * KC],   g_cwlo[Dm * KC];
__device__ bf16 g_WdThi[Dm * Dm],  g_WdTlo[Dm * Dm];
__device__ float g_p0[Dm * Dm];
__device__ bf16 g_xghi[Dm * Dm],   g_xglo[Dm * Dm];
__device__ bf16 g_cBhi[Dm * KC],   g_cBlo[Dm * KC];
__device__ float g_xc[Dm * Dm];
__device__ bf16 g_xchi[Dm * Dm],   g_xclo[Dm * Dm];
__device__ float g_delta[Dm * Dm];
__device__ float g_Bm[Dm * Ns], g_Cm[Dm * Ns];
__device__ bf16 g_yhi[Dm * Dm],    g_ylo[Dm * Dm];
__device__ bf16 g_thi[Dm * Dm],    g_tlo[Dm * Dm];

__device__ __forceinline__ float sigmoidf_(float x) {
    return 1.0f / (1.0f + expf(-x));
}

__device__ __forceinline__ uint32_t smem_u32(const void* p) {
    uint32_t a;
    asm("{ .reg .u64 t; cvta.to.shared.u64 t, %1; cvt.u32.u64 %0, t; }" : "=r"(a) : "l"(p));
    return a;
}

#define SWZ(x) ((x) ^ (((x) >> 3) & 0x70))

__device__ __forceinline__ void cpa16(uint32_t dst, const void* src) {
    asm volatile("cp.async.cg.shared.global [%0], [%1], 16;" :: "r"(dst), "l"(src));
}

#define MMA_BF16(c, a, b0, b1)                                                   \
    asm volatile(                                                                \
        "mma.sync.aligned.m16n8k16.row.col.f32.bf16.bf16.f32 "                   \
        "{%0,%1,%2,%3},{%4,%5,%6,%7},{%8,%9},{%0,%1,%2,%3};"                     \
        : "+f"(c[0]), "+f"(c[1]), "+f"(c[2]), "+f"(c[3])                         \
        : "r"(a[0]), "r"(a[1]), "r"(a[2]), "r"(a[3]), "r"(b0), "r"(b1))

#define LDSM_X4(r0, r1, r2, r3, addr)                                            \
    asm volatile("ldmatrix.sync.aligned.m8n8.x4.shared.b16 {%0,%1,%2,%3}, [%4];" \
        : "=r"(r0), "=r"(r1), "=r"(r2), "=r"(r3) : "r"(addr))

// ---------------- fp32 -> (hi,lo) bf16 split (vectorized 16B stores) --------
__global__ void __launch_bounds__(256) split_k(const float* __restrict__ in,
                                               bf16* __restrict__ hi,
                                               bf16* __restrict__ lo, int n) {
    int i = (blockIdx.x * 256 + threadIdx.x) * 8;
    if (i >= n) return;
    float4 v0 = *(const float4*)(in + i);
    float4 v1 = *(const float4*)(in + i + 4);
    float vv[8] = {v0.x, v0.y, v0.z, v0.w, v1.x, v1.y, v1.z, v1.w};
    __nv_bfloat162 hb[4], lb[4];
#pragma unroll
    for (int j = 0; j < 4; j++) {
        bf16 h0 = __float2bfloat16(vv[2 * j]);
        bf16 h1 = __float2bfloat16(vv[2 * j + 1]);
        hb[j].x = h0; hb[j].y = h1;
        lb[j].x = __float2bfloat16(vv[2 * j] - __bfloat162float(h0));
        lb[j].y = __float2bfloat16(vv[2 * j + 1] - __bfloat162float(h1));
    }
    *(int4*)(hi + i) = *(int4*)hb;
    *(int4*)(lo + i) = *(int4*)lb;
}

// ---------------- transpose + split (for W_delta) ---------------------------
__global__ void __launch_bounds__(256) transpose_split_k(const float* __restrict__ In,
                                                         bf16* __restrict__ hi,
                                                         bf16* __restrict__ lo) {
    __shared__ float t[32][33];
    int x0 = blockIdx.x * 32, y0 = blockIdx.y * 32;
    int tx = threadIdx.x;
    for (int j = threadIdx.y; j < 32; j += 8)
        t[j][tx] = In[(y0 + j) * Dm + x0 + tx];
    __syncthreads();
    for (int j = threadIdx.y; j < 32; j += 8) {
        float v = t[tx][j];
        bf16 h = __float2bfloat16(v);
        size_t idx = (size_t)(x0 + j) * Dm + y0 + tx;
        hi[idx] = h;
        lo[idx] = __float2bfloat16(v - __bfloat162float(h));
    }
}

// ---------------- build conv B matrix: B[d, i*3+kk] = p0[i, d-1+kk] ----------
__global__ void __launch_bounds__(256) conv_b_build(const float* __restrict__ P0,
                                                    bf16* __restrict__ hi,
                                                    bf16* __restrict__ lo) {
    __shared__ float Xs[32][35];
    int d0 = blockIdx.x * 32, i0 = blockIdx.y * 32;
    int tid = threadIdx.x;
    for (int idx = tid; idx < 32 * 34; idx += 256) {
        int r = idx / 34, c = idx % 34;
        int gd = d0 - 1 + c;
        Xs[r][c] = (gd >= 0 && gd < Dm) ? P0[(size_t)(i0 + r) * Dm + gd] : 0.0f;
    }
    __syncthreads();
    int i = tid & 31;
    for (int dl = tid >> 5; dl < 32; dl += 8) {
        size_t base = (size_t)(d0 + dl) * KC + (size_t)(i0 + i) * 3;
#pragma unroll
        for (int kk = 0; kk < 3; kk++) {
            float x = Xs[i][dl + kk];
            bf16 h = __float2bfloat16(x);
            hi[base + kk] = h;
            lo[base + kk] = __float2bfloat16(x - __bfloat162float(h));
        }
    }
}

// ---------------- bf16-split HMMA GEMM, deep cp.async pipeline ---------------
// C[m,n] = sum_k A[m,k]*B[n,k]; A=Ah+Al, B=Bh+Bl; C ~= Ah*Bh + Ah*Bl + Al*Bh.
// CTA tile 128(M) x TN(N), K-block 64. NBUF smem buffers, DEPTH=NBUF-1 prefetch,
// ONE __syncthreads per stage (loads for s+DEPTH hit the buffer last read at
// s-1, protected by the top-of-loop barrier).
template <int TN, int EPI, bool BIASROW, bool WF32, bool WSPLIT, bool DUAL>
__global__ void __launch_bounds__(256, 1)
gemm_mma(const bf16* __restrict__ Ah, const bf16* __restrict__ Al,
         const bf16* __restrict__ Bh, const bf16* __restrict__ Bl,
         const float* __restrict__ bias,
         float* __restrict__ Cf, bf16* __restrict__ Chi, bf16* __restrict__ Clo,
         int Nn, int K)
{
    constexpr int OFF_AL = 16384;
    constexpr int OFF_BH = 32768;
    constexpr int BHL = TN * 128;
    constexpr int STAGEB = 32768 + TN * 256;
    constexpr int NBUF = (TN == 64) ? 4 : 3;
    constexpr int DEPTH = NBUF - 1;
    constexpr int WN = TN / 2;
    constexpr int NG = WN / 16;
    constexpr int NJ = WN / 8;

    extern __shared__ __align__(1024) char dyns[];
    const int tid = threadIdx.x;
    const int lane = tid & 31, warp = tid >> 5;
    const int m0 = blockIdx.y * 128, n0 = blockIdx.x * TN;
    const uint32_t dbase = smem_u32(dyns);
    const int S = K >> 6;

    float acc[2][NJ][4];
#pragma unroll
    for (int a = 0; a < 2; a++)
#pragma unroll
        for (int b = 0; b < NJ; b++)
#pragma unroll
            for (int c = 0; c < 4; c++) acc[a][b][c] = 0.0f;

    auto load_stage = [&](int s) {
        const uint32_t sb = dbase + (s % NBUF) * STAGEB;
        const int k0 = s << 6;
#pragma unroll
        for (int i = 0; i < 4; i++) {
            int q = tid + (i << 8);
            int r = q >> 3, c = q & 7;
            uint32_t so = SWZ((uint32_t)(r * 128 + c * 16));
            size_t ga = (size_t)(m0 + r) * K + k0 + c * 8;
            cpa16(sb + so, Ah + ga);
            cpa16(sb + OFF_AL + so, Al + ga);
        }
#pragma unroll
        for (int i = 0; i < TN / 32; i++) {
            int q = tid + (i << 8);
            int r = q >> 3, c = q & 7;
            uint32_t so = SWZ((uint32_t)(r * 128 + c * 16));
            size_t gb = (size_t)(n0 + r) * K + k0 + c * 8;
            cpa16(sb + OFF_BH + so, Bh + gb);
            cpa16(sb + OFF_BH + BHL + so, Bl + gb);
        }
        asm volatile("cp.async.commit_group;" ::: "memory");
    };

#pragma unroll
    for (int s = 0; s < DEPTH; s++) load_stage(s);

    const int wm = (warp & 3) * 32, wn = (warp >> 2) * WN;
    const uint32_t frow = (lane & 7) + ((lane >> 3) & 1) * 8;
    const uint32_t fxor = (frow & 7) << 4;
    const uint32_t fcol = (lane >> 4) << 4;

    for (int s = 0; s < S; s++) {
        asm volatile("cp.async.wait_group %0;" :: "n"(DEPTH - 1) : "memory");
        __syncthreads();
        if (s + DEPTH < S) load_stage(s + DEPTH);
        else asm volatile("cp.async.commit_group;" ::: "memory");

        const uint32_t sb = dbase + (s % NBUF) * STAGEB;
#pragma unroll
        for (int ks = 0; ks < 4; ks++) {
            const uint32_t kc = (uint32_t)(ks * 32 + fcol) ^ fxor;
            uint32_t ahb[2][4], alb[2][4], bhb[NG][4], blb[NG][4];
#pragma unroll
            for (int mi = 0; mi < 2; mi++) {
                uint32_t ra = sb + (wm + mi * 16 + frow) * 128 + kc;
                LDSM_X4(ahb[mi][0], ahb[mi][1], ahb[mi][2], ahb[mi][3], ra);
                LDSM_X4(alb[mi][0], alb[mi][1], alb[mi][2], alb[mi][3], ra + OFF_AL);
            }
#pragma unroll
            for (int ni = 0; ni < NG; ni++) {
                uint32_t rb = sb + OFF_BH + (wn + ni * 16 + frow) * 128 + kc;
                LDSM_X4(bhb[ni][0], bhb[ni][1], bhb[ni][2], bhb[ni][3], rb);
                LDSM_X4(blb[ni][0], blb[ni][1], blb[ni][2], blb[ni][3], rb + BHL);
            }
            // term-major: maximize independent MMAs between accumulator reuse
#pragma unroll
            for (int mi = 0; mi < 2; mi++)
#pragma unroll
                for (int nj = 0; nj < NJ; nj++)
                    MMA_BF16(acc[mi][nj], ahb[mi], bhb[nj >> 1][nj & 1], bhb[nj >> 1][(nj & 1) + 2]);
#pragma unroll
            for (int mi = 0; mi < 2; mi++)
#pragma unroll
                for (int nj = 0; nj < NJ; nj++)
                    MMA_BF16(acc[mi][nj], ahb[mi], blb[nj >> 1][nj & 1], blb[nj >> 1][(nj & 1) + 2]);
#pragma unroll
            for (int mi = 0; mi < 2; mi++)
#pragma unroll
                for (int nj = 0; nj < NJ; nj++)
                    MMA_BF16(acc[mi][nj], alb[mi], bhb[nj >> 1][nj & 1], bhb[nj >> 1][(nj & 1) + 2]);
        }
    }

    // ---------------- epilogue ------------------------------------------------
    const int gr = lane >> 2, gc = lane & 3;
    const bool second = DUAL && (m0 >= Dm);
#pragma unroll
    for (int mi = 0; mi < 2; mi++) {
#pragma unroll
        for (int half = 0; half < 2; half++) {
            const int m = m0 + wm + mi * 16 + gr + half * 8;
            const int mrow = second ? (m - Dm) : m;
            float bm = 0.0f;
            if ((EPI == 1 || EPI == 2) && BIASROW) bm = bias[m];
#pragma unroll
            for (int nj = 0; nj < NJ; nj++) {
                const int n = n0 + wn + nj * 8 + 2 * gc;
                float v0 = acc[mi][nj][half * 2 + 0];
                float v1 = acc[mi][nj][half * 2 + 1];
                if (EPI == 1 || EPI == 2) {
                    if (BIASROW) { v0 += bm; v1 += bm; }
                    else         { v0 += bias[n]; v1 += bias[n + 1]; }
                }
                if (EPI == 2 || (DUAL && second)) {
                    v0 *= sigmoidf_(v0); v1 *= sigmoidf_(v1);
                }
                if (EPI == 3) {
                    v0 = fmaxf(v0, 0.0f) + log1pf(expf(-fabsf(v0)));
                    v1 = fmaxf(v1, 0.0f) + log1pf(expf(-fabsf(v1)));
                }
                size_t idx = (size_t)mrow * Nn + n;
                const bool wf = WF32 && !(DUAL && second);
                const bool ws = (WSPLIT && !DUAL) || (DUAL && second);
                if (wf) *(float2*)&Cf[idx] = make_float2(v0, v1);
                if (ws) {
                    bf16 h0 = __float2bfloat16(v0);
                    bf16 h1 = __float2bfloat16(v1);
                    __nv_bfloat162 hh; hh.x = h0; hh.y = h1;
                    __nv_bfloat162 ll;
                    ll.x = __float2bfloat16(v0 - __bfloat162float(h0));
                    ll.y = __float2bfloat16(v1 - __bfloat162float(h1));
                    *(__nv_bfloat162*)&Chi[idx] = hh;
                    *(__nv_bfloat162*)&Clo[idx] = ll;
                }
            }
        }
    }
}

// ---------------- B/C projections: [L,D] @ [D,16] ---------------------------
__global__ void __launch_bounds__(256) bc_kernel(const float* __restrict__ Xc,
                                                 const float* __restrict__ WB,
                                                 const float* __restrict__ WC,
                                                 float* __restrict__ Bo,
                                                 float* __restrict__ Co) {
    __shared__ float row[Dm];
    const int l = blockIdx.x;
    for (int k = threadIdx.x; k < Dm; k += 256) row[k] = Xc[(size_t)l * Dm + k];
    __syncthreads();
    const int part = threadIdx.x & 7;
    const int out = threadIdx.x >> 3;   // 0..31
    const int n = out & 15;
    const float* W = (out < 16) ? WB : WC;
    float s = 0.0f;
    for (int k = part; k < Dm; k += 8) s = fmaf(row[k], W[k * Ns + n], s);
#pragma unroll
    for (int off = 4; off; off >>= 1) s += __shfl_down_sync(0xffffffffu, s, off, 8);
    if (part == 0) {
        if (out < 16) Bo[l * Ns + n] = s;
        else          Co[l * Ns + n] = s;
    }
}

// ---------------- selective scan (emits split-bf16 y) ------------------------
__global__ void __launch_bounds__(128) scan_kernel(const float* __restrict__ delta,
                                                   const float* __restrict__ Xc,
                                                   const float* __restrict__ Bm,
                                                   const float* __restrict__ Cm,
                                                   const float* __restrict__ Alog,
                                                   bf16* __restrict__ Yhi,
                                                   bf16* __restrict__ Ylo) {
    const int n = threadIdx.x & 15;
    const int d = blockIdx.x * 8 + (threadIdx.x >> 4);
    const float a = -expf(Alog[d * Ns + n]);
    float h = 0.0f;
    for (int l = 0; l < Dm; l++) {
        float de = delta[(size_t)l * Dm + d];
        float xv = Xc[(size_t)l * Dm + d];
        float bv = Bm[l * Ns + n];
        float cv = Cm[l * Ns + n];
        float e = __expf(de * a);
        h = fmaf(e, h, de * xv * bv);
        float p = h * cv;
#pragma unroll
        for (int off = 8; off; off >>= 1) p += __shfl_down_sync(0xffffffffu, p, off, 16);
        if (n == 0) {
            bf16 hh = __float2bfloat16(p);
            size_t idx = (size_t)l * Dm + d;
            Yhi[idx] = hh;
            Ylo[idx] = __float2bfloat16(p - __bfloat162float(hh));
        }
    }
}

// ---------------- launch ------------------------------------------------------
extern "C" void kernel_launch(void* const* d_in, const int* in_sizes, int n_in,
                              void* d_out, int out_size) {
    const float* x    = (const float*)d_in[0];
    const float* Wp   = (const float*)d_in[1];
    const float* bp   = (const float*)d_in[2];
    const float* cw   = (const float*)d_in[3];
    const float* cb   = (const float*)d_in[4];
    const float* Alog = (const float*)d_in[5];
    const float* Wd   = (const float*)d_in[6];
    const float* WB   = (const float*)d_in[7];
    const float* WC   = (const float*)d_in[8];
    float* out = (float*)d_out;

    bf16 *xhi, *xlo, *Wphi, *Wplo, *cwhi, *cwlo, *WdThi, *WdTlo;
    bf16 *xghi, *xglo, *cBhi, *cBlo, *xchi, *xclo, *yhi, *ylo, *thi, *tlo;
    float *p0, *xc, *del, *Bm, *Cm;
    cudaGetSymbolAddress((void**)&xhi, g_xhi);   cudaGetSymbolAddress((void**)&xlo, g_xlo);
    cudaGetSymbolAddress((void**)&Wphi, g_Wphi); cudaGetSymbolAddress((void**)&Wplo, g_Wplo);
    cudaGetSymbolAddress((void**)&cwhi, g_cwhi); cudaGetSymbolAddress((void**)&cwlo, g_cwlo);
    cudaGetSymbolAddress((void**)&WdThi, g_WdThi); cudaGetSymbolAddress((void**)&WdTlo, g_WdTlo);
    cudaGetSymbolAddress((void**)&xghi, g_xghi); cudaGetSymbolAddress((void**)&xglo, g_xglo);
    cudaGetSymbolAddress((void**)&cBhi, g_cBhi); cudaGetSymbolAddress((void**)&cBlo, g_cBlo);
    cudaGetSymbolAddress((void**)&xchi, g_xchi); cudaGetSymbolAddress((void**)&xclo, g_xclo);
    cudaGetSymbolAddress((void**)&yhi, g_yhi);   cudaGetSymbolAddress((void**)&ylo, g_ylo);
    cudaGetSymbolAddress((void**)&thi, g_thi);   cudaGetSymbolAddress((void**)&tlo, g_tlo);
    cudaGetSymbolAddress((void**)&p0, g_p0);
    cudaGetSymbolAddress((void**)&xc, g_xc);
    cudaGetSymbolAddress((void**)&del, g_delta);
    cudaGetSymbolAddress((void**)&Bm, g_Bm);
    cudaGetSymbolAddress((void**)&Cm, g_Cm);

    const int SMEM64  = 4 * (32768 + 64 * 256);   // 196608 (4 buffers)
    const int SMEM128 = 3 * (32768 + 128 * 256);  // 196608 (3 buffers)
    cudaFuncSetAttribute(gemm_mma<128, 1, false, true,  true,  true>,  cudaFuncAttributeMaxDynamicSharedMemorySize, SMEM128);
    cudaFuncSetAttribute(gemm_mma<64,  2, true,  true,  true,  false>, cudaFuncAttributeMaxDynamicSharedMemorySize, SMEM64);
    cudaFuncSetAttribute(gemm_mma<64,  3, false, true,  false, false>, cudaFuncAttributeMaxDynamicSharedMemorySize, SMEM64);
    cudaFuncSetAttribute(gemm_mma<64,  0, false, false, true,  false>, cudaFuncAttributeMaxDynamicSharedMemorySize, SMEM64);
    cudaFuncSetAttribute(gemm_mma<64,  1, false, true,  false, false>, cudaFuncAttributeMaxDynamicSharedMemorySize, SMEM64);

    // #1..#3: splits needed by the proj GEMM
    split_k<<<(2 * Dm * Dm) / 2048, 256>>>(x, xhi, xlo, 2 * Dm * Dm);
    split_k<<<(Dm * Dm) / 2048, 256>>>(Wp, Wphi, Wplo, Dm * Dm);
    transpose_split_k<<<dim3(32, 32), dim3(32, 8)>>>(Wd, WdThi, WdTlo);

    // #4 (ncu-profiled slot): fused input projections, M=2048, tile 128x128.
    // rows <1024 -> p0 (f32,+bias); >=1024 -> xg (silu,split)
    gemm_mma<128, 1, false, true, true, true><<<dim3(8, 16), 256, SMEM128>>>(
        xhi, xlo, Wphi, Wplo, bp, p0, xghi, xglo, Dm, Dm);

    // #5..#6: conv operand prep
    split_k<<<(Dm * KC) / 2048, 256>>>(cw, cwhi, cwlo, Dm * KC);
    conv_b_build<<<dim3(32, 32), 256>>>(p0, cBhi, cBlo);

    // conv as GEMM (K = 3072)
    gemm_mma<64, 2, true, true, true, false><<<dim3(16, 8), 256, SMEM64>>>(
        cwhi, cwlo, cBhi, cBlo, cb, xc, xchi, xclo, Dm, KC);

    // delta = softplus(xc @ W_delta)
    gemm_mma<64, 3, false, true, false, false><<<dim3(16, 8), 256, SMEM64>>>(
        xchi, xclo, WdThi, WdTlo, nullptr, del, nullptr, nullptr, Dm, Dm);

    // B, C projections + scan
    bc_kernel<<<Dm, 256>>>(xc, WB, WC, Bm, Cm);
    scan_kernel<<<Dm / 8, 128>>>(del, xc, Bm, Cm, Alog, yhi, ylo);

    // t = y @ xg^T
    gemm_mma<64, 0, false, false, true, false><<<dim3(16, 8), 256, SMEM64>>>(
        yhi, ylo, xghi, xglo, nullptr, nullptr, thi, tlo, Dm, Dm);

    // out = t @ Wp^T + b
    gemm_mma<64, 1, false, true, false, false><<<dim3(16, 8), 256, SMEM64>>>(
        thi, tlo, Wphi, Wplo, bp, out, nullptr, nullptr, Dm, Dm);
}